// round 9
// baseline (speedup 1.0000x reference)
#include <cuda_runtime.h>
#include <math.h>

#define BB 32
#define SS 64
#define TT 64
#define EE 512
#define HH 1024
#define H4 4096
#define VTV 32000

typedef unsigned long long ull;

// ---------------- scratch: __device__ globals (no allocation allowed) ----------------
__device__ float g_enc_xg[SS * BB * H4];        // (s,b,4H)  encoder input-gate precompute
__device__ float g_dxg[(TT - 1) * BB * H4];     // (d,b,4H)  decoder embedding-gate precompute
__device__ float g_enc_out[BB * SS * HH];       // (b,s,H)
__device__ float g_enc_pre[BB * SS * HH];       // (b,s,H)   enc_out @ We^T + attn_b
__device__ float g_hhist[(TT - 1) * BB * HH];   // (d,b,H)   decoder h history for fc GEMM
__device__ float g_h[BB * HH];
__device__ float g_c[BB * HH];
__device__ float g_hW[BB * HH];                 // h @ Wh^T
__device__ float g_ctx[BB * HH];
__device__ float g_gates[BB * H4];
__device__ float g_encb[H4];
__device__ float g_decb[H4];
__device__ int   g_sidx[SS * BB];               // row m=s*32+b -> src[b,s]
__device__ int   g_tidx[(TT - 1) * BB];         // row m=d*32+b -> tgt[b,d]

__device__ __forceinline__ float sigf(float x) { return 1.f / (1.f + expf(-x)); }
__device__ __forceinline__ float tanh_fast(float x) {
    float y; asm("tanh.approx.f32 %0, %1;" : "=f"(y) : "f"(x)); return y;
}

// ---------------- init: zero out[:,0,:], zero h/c, gather indices, fuse biases -------
__global__ void init_kernel(float* __restrict__ out,
                            const int* __restrict__ src, const int* __restrict__ tgt,
                            const float* __restrict__ ebih, const float* __restrict__ ebhh,
                            const float* __restrict__ dbih, const float* __restrict__ dbhh)
{
    int idx = blockIdx.x * blockDim.x + threadIdx.x;
    if (idx < BB * VTV) {
        int b = idx / VTV, v = idx % VTV;
        out[(size_t)b * TT * VTV + v] = 0.f;   // t = 0 row is zeros
    }
    if (idx < BB * HH) { g_h[idx] = 0.f; g_c[idx] = 0.f; }
    if (idx < SS * BB) { int s = idx >> 5, b = idx & 31; g_sidx[idx] = src[b * SS + s]; }
    if (idx < (TT - 1) * BB) { int d = idx >> 5, b = idx & 31; g_tidx[idx] = tgt[b * TT + d]; }
    if (idx < H4) {
        g_encb[idx] = ebih[idx] + ebhh[idx];
        g_decb[idx] = dbih[idx] + dbhh[idx];
    }
}

// ---------------- big NT GEMM: C[m,n] = sum_k A[m,k]*B[n,k] (f32x2 inner) ------------
// EPI: 0 = plain store, 1 = +bias[n], 4 = scatter into out[b, d+1, n] with +bias[n]
template<int EPI, bool GATHER>
__global__ void __launch_bounds__(256)
gemm_big(const float* __restrict__ A, int lda,
         const float* __restrict__ Bw, int ldb,
         float* __restrict__ C, int ldc,
         int M, int N, int K,
         const float* __restrict__ bias,
         const int* __restrict__ gidx)
{
    constexpr int BM = 128, BN = 64, BK = 16, TM = 8;
    __shared__ __align__(16) float As[BK][BM + 4];
    __shared__ __align__(16) float Bs[BK][BN + 4];

    const int tid = threadIdx.x;
    const int bm = blockIdx.y * BM;
    const int bn = blockIdx.x * BN;
    const int tx = tid % 16;          // 16 col-groups of TN=4
    const int ty = tid / 16;          // 16 row-groups of TM=8

    ull acc[TM][2];
#pragma unroll
    for (int i = 0; i < TM; i++) { acc[i][0] = 0ull; acc[i][1] = 0ull; }

    for (int k0 = 0; k0 < K; k0 += BK) {
        __syncthreads();
#pragma unroll
        for (int it = 0; it < 2; it++) {              // A tile: 128x16 = 512 float4
            int i = tid + it * 256;
            int r = i / 4, c = (i % 4) * 4;
            int gm = bm + r; if (gm > M - 1) gm = M - 1;
            const float* arow = GATHER ? (A + (size_t)gidx[gm] * lda)
                                       : (A + (size_t)gm * lda);
            float4 v = *reinterpret_cast<const float4*>(arow + k0 + c);
            As[c + 0][r] = v.x; As[c + 1][r] = v.y;
            As[c + 2][r] = v.z; As[c + 3][r] = v.w;
        }
        {                                             // B tile: 64x16 = 256 float4
            int r = tid / 4, c = (tid % 4) * 4;
            float4 w = *reinterpret_cast<const float4*>(Bw + (size_t)(bn + r) * ldb + k0 + c);
            Bs[c + 0][r] = w.x; Bs[c + 1][r] = w.y;
            Bs[c + 2][r] = w.z; Bs[c + 3][r] = w.w;
        }
        __syncthreads();
#pragma unroll
        for (int kk = 0; kk < BK; kk++) {
            ull b0 = *reinterpret_cast<const ull*>(&Bs[kk][tx * 4]);
            ull b1 = *reinterpret_cast<const ull*>(&Bs[kk][tx * 4 + 2]);
#pragma unroll
            for (int i = 0; i < TM; i++) {
                float a = As[kk][ty * TM + i];
                ull a2;
                asm("mov.b64 %0, {%1, %1};" : "=l"(a2) : "f"(a));
                asm("fma.rn.f32x2 %0, %1, %2, %0;" : "+l"(acc[i][0]) : "l"(a2), "l"(b0));
                asm("fma.rn.f32x2 %0, %1, %2, %0;" : "+l"(acc[i][1]) : "l"(a2), "l"(b1));
            }
        }
    }

#pragma unroll
    for (int i = 0; i < TM; i++) {
        int gm = bm + ty * TM + i;
        if (gm >= M) continue;
#pragma unroll
        for (int j = 0; j < 2; j++) {
            float2 v = *reinterpret_cast<float2*>(&acc[i][j]);
            int gn = bn + tx * 4 + 2 * j;
            if (EPI == 0) {
                C[(size_t)gm * ldc + gn]     = v.x;
                C[(size_t)gm * ldc + gn + 1] = v.y;
            } else if (EPI == 1) {
                C[(size_t)gm * ldc + gn]     = v.x + bias[gn];
                C[(size_t)gm * ldc + gn + 1] = v.y + bias[gn + 1];
            } else {  // EPI == 4: row gm = d*32 + b  ->  out[b, d+1, :]
                int b = gm & 31, d = gm >> 5;
                size_t o = ((size_t)b * TT + d + 1) * VTV + gn;
                C[o]     = v.x + bias[gn];
                C[o + 1] = v.y + bias[gn + 1];
            }
        }
    }
}

// ---------------- small recurrent GEMM: M=32, C[b,n] = sum_k A[b,k]*B[n,k] ----------
// DUAL: accumulate a second (A1,B1) pass.  ADDX: epilogue adds bias[n] + xg[b*N+n].
template<bool DUAL, bool ADDX>
__global__ void __launch_bounds__(256)
rec_gemm(const float* __restrict__ A0, const float* __restrict__ B0, int ldb0,
         const float* __restrict__ A1, const float* __restrict__ B1, int ldb1,
         float* __restrict__ C, int N, int K,
         const float* __restrict__ bias, const float* __restrict__ xg)
{
    constexpr int BK = 32;
    __shared__ __align__(16) float As[BK][36];
    __shared__ __align__(16) float Bs[BK][36];

    const int tid = threadIdx.x;
    const int bn = blockIdx.x * 32;
    const int tx = tid % 16;   // cols: tx*2
    const int ty = tid / 16;   // rows: ty*2

    ull acc[2]; acc[0] = 0ull; acc[1] = 0ull;

    const int npass = DUAL ? 2 : 1;
    for (int p = 0; p < npass; p++) {
        const float* A  = p ? A1 : A0;
        const float* Bw = p ? B1 : B0;
        const int ldb   = p ? ldb1 : ldb0;
        for (int k0 = 0; k0 < K; k0 += BK) {
            __syncthreads();
            {
                int r = tid / 8, c = (tid % 8) * 4;     // 32 rows x 32 k
                float4 v = *reinterpret_cast<const float4*>(A + (size_t)r * K + k0 + c);
                As[c + 0][r] = v.x; As[c + 1][r] = v.y;
                As[c + 2][r] = v.z; As[c + 3][r] = v.w;
                float4 w = *reinterpret_cast<const float4*>(Bw + (size_t)(bn + r) * ldb + k0 + c);
                Bs[c + 0][r] = w.x; Bs[c + 1][r] = w.y;
                Bs[c + 2][r] = w.z; Bs[c + 3][r] = w.w;
            }
            __syncthreads();
#pragma unroll
            for (int kk = 0; kk < BK; kk++) {
                ull b = *reinterpret_cast<const ull*>(&Bs[kk][tx * 2]);
                float a0 = As[kk][ty * 2], a1 = As[kk][ty * 2 + 1];
                ull a2;
                asm("mov.b64 %0, {%1, %1};" : "=l"(a2) : "f"(a0));
                asm("fma.rn.f32x2 %0, %1, %2, %0;" : "+l"(acc[0]) : "l"(a2), "l"(b));
                asm("mov.b64 %0, {%1, %1};" : "=l"(a2) : "f"(a1));
                asm("fma.rn.f32x2 %0, %1, %2, %0;" : "+l"(acc[1]) : "l"(a2), "l"(b));
            }
        }
    }

#pragma unroll
    for (int i = 0; i < 2; i++) {
        int gm = ty * 2 + i;
        int gn = bn + tx * 2;
        float2 v = *reinterpret_cast<float2*>(&acc[i]);
        if (ADDX) {
            v.x += bias[gn]     + xg[(size_t)gm * N + gn];
            v.y += bias[gn + 1] + xg[(size_t)gm * N + gn + 1];
        }
        C[(size_t)gm * N + gn]     = v.x;
        C[(size_t)gm * N + gn + 1] = v.y;
    }
}

// ---------------- attention: tanh-scores + softmax + context (1 block / batch) ------
__global__ void __launch_bounds__(256) attn_kernel(const float* __restrict__ vW)
{
    __shared__ float shW[HH];
    __shared__ float sv[HH];
    __shared__ float sc[SS];
    const int b = blockIdx.x;
    const int tid = threadIdx.x;
    const int lane = tid & 31, warp = tid >> 5;

    for (int j = tid; j < HH; j += 256) { shW[j] = g_hW[b * HH + j]; sv[j] = vW[j]; }
    __syncthreads();

    for (int s = warp; s < SS; s += 8) {
        const float* ep = g_enc_pre + ((size_t)b * SS + s) * HH;
        float acc = 0.f;
        for (int j = lane; j < HH; j += 32)
            acc += sv[j] * tanh_fast(shW[j] + ep[j]);
#pragma unroll
        for (int o = 16; o; o >>= 1) acc += __shfl_xor_sync(0xffffffffu, acc, o);
        if (lane == 0) sc[s] = acc;
    }
    __syncthreads();

    if (tid == 0) {
        float mx = sc[0];
        for (int s = 1; s < SS; s++) mx = fmaxf(mx, sc[s]);
        float sum = 0.f;
        for (int s = 0; s < SS; s++) { float e = expf(sc[s] - mx); sc[s] = e; sum += e; }
        float inv = 1.f / sum;
        for (int s = 0; s < SS; s++) sc[s] *= inv;
    }
    __syncthreads();

    for (int j = tid; j < HH; j += 256) {
        float acc = 0.f;
        const float* eo = g_enc_out + (size_t)b * SS * HH + j;
#pragma unroll 8
        for (int s = 0; s < SS; s++) acc += sc[s] * eo[(size_t)s * HH];
        g_ctx[b * HH + j] = acc;
    }
}

// ---------------- LSTM cell elementwise (PyTorch gate order i,f,g,o) ----------------
__global__ void __launch_bounds__(256) lstm_kernel(float* __restrict__ hdst, int bstride)
{
    int idx = blockIdx.x * blockDim.x + threadIdx.x;
    if (idx >= BB * HH) return;
    int b = idx >> 10, j = idx & (HH - 1);
    const float* g = g_gates + (size_t)b * H4;
    float gi = g[j], gf = g[j + HH], gg = g[j + 2 * HH], go = g[j + 3 * HH];
    float c  = g_c[idx];
    float cn = sigf(gf) * c + sigf(gi) * tanhf(gg);
    float hn = sigf(go) * tanhf(cn);
    g_c[idx] = cn;
    g_h[idx] = hn;
    hdst[(size_t)b * bstride + j] = hn;
}

// ------------------------------------- launch ---------------------------------------
extern "C" void kernel_launch(void* const* d_in, const int* in_sizes, int n_in,
                              void* d_out, int out_size)
{
    const int*   src     = (const int*)d_in[0];
    const int*   tgt     = (const int*)d_in[1];
    const float* enc_emb = (const float*)d_in[2];
    const float* enc_Wih = (const float*)d_in[3];
    const float* enc_Whh = (const float*)d_in[4];
    const float* enc_bih = (const float*)d_in[5];
    const float* enc_bhh = (const float*)d_in[6];
    const float* dec_emb = (const float*)d_in[7];
    const float* attn_W  = (const float*)d_in[8];
    const float* attn_b  = (const float*)d_in[9];
    const float* v_W     = (const float*)d_in[10];
    const float* dec_Wih = (const float*)d_in[11];
    const float* dec_Whh = (const float*)d_in[12];
    const float* dec_bih = (const float*)d_in[13];
    const float* dec_bhh = (const float*)d_in[14];
    const float* fc_W    = (const float*)d_in[15];
    const float* fc_b    = (const float*)d_in[16];
    float* out = (float*)d_out;

    void *pxg, *pdxg, *peo, *pep, *phh, *ph, *pctx, *pg, *phw, *peb, *pdb, *psi, *pti;
    cudaGetSymbolAddress(&pxg,  g_enc_xg);
    cudaGetSymbolAddress(&pdxg, g_dxg);
    cudaGetSymbolAddress(&peo,  g_enc_out);
    cudaGetSymbolAddress(&pep,  g_enc_pre);
    cudaGetSymbolAddress(&phh,  g_hhist);
    cudaGetSymbolAddress(&ph,   g_h);
    cudaGetSymbolAddress(&pctx, g_ctx);
    cudaGetSymbolAddress(&pg,   g_gates);
    cudaGetSymbolAddress(&phw,  g_hW);
    cudaGetSymbolAddress(&peb,  g_encb);
    cudaGetSymbolAddress(&pdb,  g_decb);
    cudaGetSymbolAddress(&psi,  g_sidx);
    cudaGetSymbolAddress(&pti,  g_tidx);

    float* f_xg  = (float*)pxg;   float* f_dxg = (float*)pdxg;
    float* f_eo  = (float*)peo;   float* f_ep  = (float*)pep;
    float* f_hh  = (float*)phh;   float* f_h   = (float*)ph;
    float* f_ctx = (float*)pctx;  float* f_g   = (float*)pg;
    float* f_hw  = (float*)phw;   float* f_eb  = (float*)peb;
    float* f_db  = (float*)pdb;
    int*   i_si  = (int*)psi;     int*   i_ti  = (int*)pti;

    // 1. init
    init_kernel<<<(BB * VTV + 255) / 256, 256>>>(out, src, tgt,
                                                 enc_bih, enc_bhh, dec_bih, dec_bhh);

    // 2. encoder input gates: (s*32+b, 4H) = enc_emb[src] @ enc_Wih^T
    {
        dim3 grid(H4 / 64, (SS * BB + 127) / 128);
        gemm_big<0, true><<<grid, 256>>>(enc_emb, EE, enc_Wih, EE,
                                         f_xg, H4, SS * BB, H4, EE, nullptr, i_si);
    }
    // 3. decoder embedding gates: (d*32+b, 4H) = dec_emb[tgt] @ dec_Wih[:, :E]^T
    {
        dim3 grid(H4 / 64, ((TT - 1) * BB + 127) / 128);
        gemm_big<0, true><<<grid, 256>>>(dec_emb, EE, dec_Wih, EE + HH,
                                         f_dxg, H4, (TT - 1) * BB, H4, EE, nullptr, i_ti);
    }

    // 4. encoder recurrence
    for (int s = 0; s < SS; s++) {
        rec_gemm<false, true><<<H4 / 32, 256>>>(f_h, enc_Whh, HH,
                                                nullptr, nullptr, 0,
                                                f_g, H4, HH, f_eb,
                                                f_xg + (size_t)s * BB * H4);
        lstm_kernel<<<BB * HH / 256, 256>>>(f_eo + (size_t)s * HH, SS * HH);
    }

    // 5. enc_pre = enc_out @ We^T + attn_b   (We = attn_W[:, H:2H])
    {
        dim3 grid(HH / 64, (BB * SS + 127) / 128);
        gemm_big<1, false><<<grid, 256>>>(f_eo, HH, attn_W + HH, 2 * HH,
                                          f_ep, HH, BB * SS, HH, HH, attn_b, nullptr);
    }

    // 6. decoder recurrence (teacher forced)
    for (int d = 0; d < TT - 1; d++) {
        rec_gemm<false, false><<<HH / 32, 256>>>(f_h, attn_W, 2 * HH,
                                                 nullptr, nullptr, 0,
                                                 f_hw, HH, HH, nullptr, nullptr);
        attn_kernel<<<BB, 256>>>(v_W);
        rec_gemm<true, true><<<H4 / 32, 256>>>(f_ctx, dec_Wih + EE, EE + HH,
                                               f_h, dec_Whh, HH,
                                               f_g, H4, HH, f_db,
                                               f_dxg + (size_t)d * BB * H4);
        lstm_kernel<<<BB * HH / 256, 256>>>(f_hh + (size_t)d * BB * HH, HH);
    }

    // 7. fc logits: out[b, d+1, :] = h_hist @ fc_W^T + fc_b
    {
        dim3 grid(VTV / 64, ((TT - 1) * BB + 127) / 128);
        gemm_big<4, false><<<grid, 256>>>(f_hh, HH, fc_W, HH,
                                          out, VTV, (TT - 1) * BB, VTV, HH, fc_b, nullptr);
    }
}

// round 11
// speedup vs baseline: 1.0014x; 1.0014x over previous
#include <cuda_runtime.h>
#include <math.h>

#define BB 32
#define SS 64
#define TT 64
#define EE 512
#define HH 1024
#define H4 4096
#define VTV 32000

typedef unsigned long long ull;

// ---------------- scratch: __device__ globals (no allocation allowed) ----------------
__device__ float g_enc_xg[SS * BB * H4];        // (s,b,4H)  encoder input-gate precompute
__device__ float g_dxg[(TT - 1) * BB * H4];     // (d,b,4H)  decoder embedding-gate precompute
__device__ float g_enc_out[BB * SS * HH];       // (b,s,H)
__device__ float g_enc_pre[BB * SS * HH];       // (b,s,H)   enc_out @ We^T + attn_b
__device__ float g_hhist[(TT - 1) * BB * HH];   // (d,b,H)   decoder h history for fc GEMM
__device__ float g_h[BB * HH];
__device__ float g_c[BB * HH];
__device__ float g_hW[BB * HH];                 // h @ Wh^T
__device__ float g_ctx[BB * HH];
__device__ float g_gates[BB * H4];
__device__ float g_encb[H4];
__device__ float g_decb[H4];
__device__ int   g_sidx[SS * BB];               // row m=s*32+b -> src[b,s]
__device__ int   g_tidx[(TT - 1) * BB];         // row m=d*32+b -> tgt[b,d]

__device__ __forceinline__ float sigf(float x) { return 1.f / (1.f + expf(-x)); }
__device__ __forceinline__ float tanh_fast(float x) {
    float y; asm("tanh.approx.f32 %0, %1;" : "=f"(y) : "f"(x)); return y;
}

// ---------------- init: zero out[:,0,:], zero h/c, gather indices, fuse biases -------
__global__ void init_kernel(float* __restrict__ out,
                            const int* __restrict__ src, const int* __restrict__ tgt,
                            const float* __restrict__ ebih, const float* __restrict__ ebhh,
                            const float* __restrict__ dbih, const float* __restrict__ dbhh)
{
    int idx = blockIdx.x * blockDim.x + threadIdx.x;
    if (idx < BB * VTV) {
        int b = idx / VTV, v = idx % VTV;
        out[(size_t)b * TT * VTV + v] = 0.f;   // t = 0 row is zeros
    }
    if (idx < BB * HH) { g_h[idx] = 0.f; g_c[idx] = 0.f; }
    if (idx < SS * BB) { int s = idx >> 5, b = idx & 31; g_sidx[idx] = src[b * SS + s]; }
    if (idx < (TT - 1) * BB) { int d = idx >> 5, b = idx & 31; g_tidx[idx] = tgt[b * TT + d]; }
    if (idx < H4) {
        g_encb[idx] = ebih[idx] + ebhh[idx];
        g_decb[idx] = dbih[idx] + dbhh[idx];
    }
}

// ---------------- big NT GEMM: C[m,n] = sum_k A[m,k]*B[n,k] (f32x2 inner) ------------
// EPI: 0 = plain store, 1 = +bias[n], 4 = scatter into out[b, d+1, n] with +bias[n]
template<int EPI, bool GATHER>
__global__ void __launch_bounds__(256)
gemm_big(const float* __restrict__ A, int lda,
         const float* __restrict__ Bw, int ldb,
         float* __restrict__ C, int ldc,
         int M, int N, int K,
         const float* __restrict__ bias,
         const int* __restrict__ gidx)
{
    constexpr int BM = 128, BN = 64, BK = 16, TM = 8;
    __shared__ __align__(16) float As[BK][BM + 4];
    __shared__ __align__(16) float Bs[BK][BN + 4];

    const int tid = threadIdx.x;
    const int bm = blockIdx.y * BM;
    const int bn = blockIdx.x * BN;
    const int tx = tid % 16;          // 16 col-groups of TN=4
    const int ty = tid / 16;          // 16 row-groups of TM=8

    ull acc[TM][2];
#pragma unroll
    for (int i = 0; i < TM; i++) { acc[i][0] = 0ull; acc[i][1] = 0ull; }

    for (int k0 = 0; k0 < K; k0 += BK) {
        __syncthreads();
#pragma unroll
        for (int it = 0; it < 2; it++) {              // A tile: 128x16 = 512 float4
            int i = tid + it * 256;
            int r = i / 4, c = (i % 4) * 4;
            int gm = bm + r; if (gm > M - 1) gm = M - 1;
            const float* arow = GATHER ? (A + (size_t)gidx[gm] * lda)
                                       : (A + (size_t)gm * lda);
            float4 v = *reinterpret_cast<const float4*>(arow + k0 + c);
            As[c + 0][r] = v.x; As[c + 1][r] = v.y;
            As[c + 2][r] = v.z; As[c + 3][r] = v.w;
        }
        {                                             // B tile: 64x16 = 256 float4
            int r = tid / 4, c = (tid % 4) * 4;
            float4 w = *reinterpret_cast<const float4*>(Bw + (size_t)(bn + r) * ldb + k0 + c);
            Bs[c + 0][r] = w.x; Bs[c + 1][r] = w.y;
            Bs[c + 2][r] = w.z; Bs[c + 3][r] = w.w;
        }
        __syncthreads();
#pragma unroll
        for (int kk = 0; kk < BK; kk++) {
            ull b0 = *reinterpret_cast<const ull*>(&Bs[kk][tx * 4]);
            ull b1 = *reinterpret_cast<const ull*>(&Bs[kk][tx * 4 + 2]);
#pragma unroll
            for (int i = 0; i < TM; i++) {
                float a = As[kk][ty * TM + i];
                ull a2;
                asm("mov.b64 %0, {%1, %1};" : "=l"(a2) : "f"(a));
                asm("fma.rn.f32x2 %0, %1, %2, %0;" : "+l"(acc[i][0]) : "l"(a2), "l"(b0));
                asm("fma.rn.f32x2 %0, %1, %2, %0;" : "+l"(acc[i][1]) : "l"(a2), "l"(b1));
            }
        }
    }

#pragma unroll
    for (int i = 0; i < TM; i++) {
        int gm = bm + ty * TM + i;
        if (gm >= M) continue;
#pragma unroll
        for (int j = 0; j < 2; j++) {
            float2 v = *reinterpret_cast<float2*>(&acc[i][j]);
            int gn = bn + tx * 4 + 2 * j;
            if (EPI == 0) {
                C[(size_t)gm * ldc + gn]     = v.x;
                C[(size_t)gm * ldc + gn + 1] = v.y;
            } else if (EPI == 1) {
                C[(size_t)gm * ldc + gn]     = v.x + bias[gn];
                C[(size_t)gm * ldc + gn + 1] = v.y + bias[gn + 1];
            } else {  // EPI == 4: row gm = d*32 + b  ->  out[b, d+1, :]
                int b = gm & 31, d = gm >> 5;
                size_t o = ((size_t)b * TT + d + 1) * VTV + gn;
                C[o]     = v.x + bias[gn];
                C[o + 1] = v.y + bias[gn + 1];
            }
        }
    }
}

// ---------------- small recurrent GEMM: M=32, C[b,n] = sum_k A[b,k]*B[n,k] ----------
// DUAL: accumulate a second (A1,B1) pass.  ADDX: epilogue adds bias[n] + xg[b*N+n].
template<bool DUAL, bool ADDX>
__global__ void __launch_bounds__(256)
rec_gemm(const float* __restrict__ A0, const float* __restrict__ B0, int ldb0,
         const float* __restrict__ A1, const float* __restrict__ B1, int ldb1,
         float* __restrict__ C, int N, int K,
         const float* __restrict__ bias, const float* __restrict__ xg)
{
    constexpr int BK = 32;
    __shared__ __align__(16) float As[BK][36];
    __shared__ __align__(16) float Bs[BK][36];

    const int tid = threadIdx.x;
    const int bn = blockIdx.x * 32;
    const int tx = tid % 16;   // cols: tx*2
    const int ty = tid / 16;   // rows: ty*2

    ull acc[2]; acc[0] = 0ull; acc[1] = 0ull;

    const int npass = DUAL ? 2 : 1;
    for (int p = 0; p < npass; p++) {
        const float* A  = p ? A1 : A0;
        const float* Bw = p ? B1 : B0;
        const int ldb   = p ? ldb1 : ldb0;
        for (int k0 = 0; k0 < K; k0 += BK) {
            __syncthreads();
            {
                int r = tid / 8, c = (tid % 8) * 4;     // 32 rows x 32 k
                float4 v = *reinterpret_cast<const float4*>(A + (size_t)r * K + k0 + c);
                As[c + 0][r] = v.x; As[c + 1][r] = v.y;
                As[c + 2][r] = v.z; As[c + 3][r] = v.w;
                float4 w = *reinterpret_cast<const float4*>(Bw + (size_t)(bn + r) * ldb + k0 + c);
                Bs[c + 0][r] = w.x; Bs[c + 1][r] = w.y;
                Bs[c + 2][r] = w.z; Bs[c + 3][r] = w.w;
            }
            __syncthreads();
#pragma unroll
            for (int kk = 0; kk < BK; kk++) {
                ull b = *reinterpret_cast<const ull*>(&Bs[kk][tx * 2]);
                float a0 = As[kk][ty * 2], a1 = As[kk][ty * 2 + 1];
                ull a2;
                asm("mov.b64 %0, {%1, %1};" : "=l"(a2) : "f"(a0));
                asm("fma.rn.f32x2 %0, %1, %2, %0;" : "+l"(acc[0]) : "l"(a2), "l"(b));
                asm("mov.b64 %0, {%1, %1};" : "=l"(a2) : "f"(a1));
                asm("fma.rn.f32x2 %0, %1, %2, %0;" : "+l"(acc[1]) : "l"(a2), "l"(b));
            }
        }
    }

#pragma unroll
    for (int i = 0; i < 2; i++) {
        int gm = ty * 2 + i;
        int gn = bn + tx * 2;
        float2 v = *reinterpret_cast<float2*>(&acc[i]);
        if (ADDX) {
            v.x += bias[gn]     + xg[(size_t)gm * N + gn];
            v.y += bias[gn + 1] + xg[(size_t)gm * N + gn + 1];
        }
        C[(size_t)gm * N + gn]     = v.x;
        C[(size_t)gm * N + gn + 1] = v.y;
    }
}

// ---------------- attention: tanh-scores + softmax + context (1 block / batch) ------
__global__ void __launch_bounds__(256) attn_kernel(const float* __restrict__ vW)
{
    __shared__ float shW[HH];
    __shared__ float sv[HH];
    __shared__ float sc[SS];
    const int b = blockIdx.x;
    const int tid = threadIdx.x;
    const int lane = tid & 31, warp = tid >> 5;

    for (int j = tid; j < HH; j += 256) { shW[j] = g_hW[b * HH + j]; sv[j] = vW[j]; }
    __syncthreads();

    for (int s = warp; s < SS; s += 8) {
        const float* ep = g_enc_pre + ((size_t)b * SS + s) * HH;
        float acc = 0.f;
        for (int j = lane; j < HH; j += 32)
            acc += sv[j] * tanh_fast(shW[j] + ep[j]);
#pragma unroll
        for (int o = 16; o; o >>= 1) acc += __shfl_xor_sync(0xffffffffu, acc, o);
        if (lane == 0) sc[s] = acc;
    }
    __syncthreads();

    if (tid == 0) {
        float mx = sc[0];
        for (int s = 1; s < SS; s++) mx = fmaxf(mx, sc[s]);
        float sum = 0.f;
        for (int s = 0; s < SS; s++) { float e = expf(sc[s] - mx); sc[s] = e; sum += e; }
        float inv = 1.f / sum;
        for (int s = 0; s < SS; s++) sc[s] *= inv;
    }
    __syncthreads();

    for (int j = tid; j < HH; j += 256) {
        float acc = 0.f;
        const float* eo = g_enc_out + (size_t)b * SS * HH + j;
#pragma unroll 8
        for (int s = 0; s < SS; s++) acc += sc[s] * eo[(size_t)s * HH];
        g_ctx[b * HH + j] = acc;
    }
}

// ---------------- LSTM cell elementwise (PyTorch gate order i,f,g,o) ----------------
__global__ void __launch_bounds__(256) lstm_kernel(float* __restrict__ hdst, int bstride)
{
    int idx = blockIdx.x * blockDim.x + threadIdx.x;
    if (idx >= BB * HH) return;
    int b = idx >> 10, j = idx & (HH - 1);
    const float* g = g_gates + (size_t)b * H4;
    float gi = g[j], gf = g[j + HH], gg = g[j + 2 * HH], go = g[j + 3 * HH];
    float c  = g_c[idx];
    float cn = sigf(gf) * c + sigf(gi) * tanhf(gg);
    float hn = sigf(go) * tanhf(cn);
    g_c[idx] = cn;
    g_h[idx] = hn;
    hdst[(size_t)b * bstride + j] = hn;
}

// ------------------------------------- launch ---------------------------------------
extern "C" void kernel_launch(void* const* d_in, const int* in_sizes, int n_in,
                              void* d_out, int out_size)
{
    const int*   src     = (const int*)d_in[0];
    const int*   tgt     = (const int*)d_in[1];
    const float* enc_emb = (const float*)d_in[2];
    const float* enc_Wih = (const float*)d_in[3];
    const float* enc_Whh = (const float*)d_in[4];
    const float* enc_bih = (const float*)d_in[5];
    const float* enc_bhh = (const float*)d_in[6];
    const float* dec_emb = (const float*)d_in[7];
    const float* attn_W  = (const float*)d_in[8];
    const float* attn_b  = (const float*)d_in[9];
    const float* v_W     = (const float*)d_in[10];
    const float* dec_Wih = (const float*)d_in[11];
    const float* dec_Whh = (const float*)d_in[12];
    const float* dec_bih = (const float*)d_in[13];
    const float* dec_bhh = (const float*)d_in[14];
    const float* fc_W    = (const float*)d_in[15];
    const float* fc_b    = (const float*)d_in[16];
    float* out = (float*)d_out;

    void *pxg, *pdxg, *peo, *pep, *phh, *ph, *pctx, *pg, *phw, *peb, *pdb, *psi, *pti;
    cudaGetSymbolAddress(&pxg,  g_enc_xg);
    cudaGetSymbolAddress(&pdxg, g_dxg);
    cudaGetSymbolAddress(&peo,  g_enc_out);
    cudaGetSymbolAddress(&pep,  g_enc_pre);
    cudaGetSymbolAddress(&phh,  g_hhist);
    cudaGetSymbolAddress(&ph,   g_h);
    cudaGetSymbolAddress(&pctx, g_ctx);
    cudaGetSymbolAddress(&pg,   g_gates);
    cudaGetSymbolAddress(&phw,  g_hW);
    cudaGetSymbolAddress(&peb,  g_encb);
    cudaGetSymbolAddress(&pdb,  g_decb);
    cudaGetSymbolAddress(&psi,  g_sidx);
    cudaGetSymbolAddress(&pti,  g_tidx);

    float* f_xg  = (float*)pxg;   float* f_dxg = (float*)pdxg;
    float* f_eo  = (float*)peo;   float* f_ep  = (float*)pep;
    float* f_hh  = (float*)phh;   float* f_h   = (float*)ph;
    float* f_ctx = (float*)pctx;  float* f_g   = (float*)pg;
    float* f_hw  = (float*)phw;   float* f_eb  = (float*)peb;
    float* f_db  = (float*)pdb;
    int*   i_si  = (int*)psi;     int*   i_ti  = (int*)pti;

    // 1. init
    init_kernel<<<(BB * VTV + 255) / 256, 256>>>(out, src, tgt,
                                                 enc_bih, enc_bhh, dec_bih, dec_bhh);

    // 2. encoder input gates: (s*32+b, 4H) = enc_emb[src] @ enc_Wih^T
    {
        dim3 grid(H4 / 64, (SS * BB + 127) / 128);
        gemm_big<0, true><<<grid, 256>>>(enc_emb, EE, enc_Wih, EE,
                                         f_xg, H4, SS * BB, H4, EE, nullptr, i_si);
    }
    // 3. decoder embedding gates: (d*32+b, 4H) = dec_emb[tgt] @ dec_Wih[:, :E]^T
    {
        dim3 grid(H4 / 64, ((TT - 1) * BB + 127) / 128);
        gemm_big<0, true><<<grid, 256>>>(dec_emb, EE, dec_Wih, EE + HH,
                                         f_dxg, H4, (TT - 1) * BB, H4, EE, nullptr, i_ti);
    }

    // 4. encoder recurrence
    for (int s = 0; s < SS; s++) {
        rec_gemm<false, true><<<H4 / 32, 256>>>(f_h, enc_Whh, HH,
                                                nullptr, nullptr, 0,
                                                f_g, H4, HH, f_eb,
                                                f_xg + (size_t)s * BB * H4);
        lstm_kernel<<<BB * HH / 256, 256>>>(f_eo + (size_t)s * HH, SS * HH);
    }

    // 5. enc_pre = enc_out @ We^T + attn_b   (We = attn_W[:, H:2H])
    {
        dim3 grid(HH / 64, (BB * SS + 127) / 128);
        gemm_big<1, false><<<grid, 256>>>(f_eo, HH, attn_W + HH, 2 * HH,
                                          f_ep, HH, BB * SS, HH, HH, attn_b, nullptr);
    }

    // 6. decoder recurrence (teacher forced)
    for (int d = 0; d < TT - 1; d++) {
        rec_gemm<false, false><<<HH / 32, 256>>>(f_h, attn_W, 2 * HH,
                                                 nullptr, nullptr, 0,
                                                 f_hw, HH, HH, nullptr, nullptr);
        attn_kernel<<<BB, 256>>>(v_W);
        rec_gemm<true, true><<<H4 / 32, 256>>>(f_ctx, dec_Wih + EE, EE + HH,
                                               f_h, dec_Whh, HH,
                                               f_g, H4, HH, f_db,
                                               f_dxg + (size_t)d * BB * H4);
        lstm_kernel<<<BB * HH / 256, 256>>>(f_hh + (size_t)d * BB * HH, HH);
    }

    // 7. fc logits: out[b, d+1, :] = h_hist @ fc_W^T + fc_b
    {
        dim3 grid(VTV / 64, ((TT - 1) * BB + 127) / 128);
        gemm_big<4, false><<<grid, 256>>>(f_hh, HH, fc_W, HH,
                                          out, VTV, (TT - 1) * BB, VTV, HH, fc_b, nullptr);
    }
}

// round 13
// speedup vs baseline: 1.2471x; 1.2454x over previous
#include <cuda_runtime.h>
#include <math.h>

#define BB 32
#define SS 64
#define TT 64
#define EE 512
#define HH 1024
#define H4 4096
#define VTV 32000
#define NKC 4            // split-K chunks for recurrent GEMMs

typedef unsigned long long ull;

// ---------------- scratch: __device__ globals (no allocation allowed) ----------------
__device__ float g_enc_xg[SS * BB * H4];        // (s,b,4H)
__device__ float g_dxg[(TT - 1) * BB * H4];     // (d,b,4H)
__device__ float g_enc_out[BB * SS * HH];       // (b,s,H)
__device__ float g_enc_pre[BB * SS * HH];       // (b,s,H)  enc_out @ We^T + attn_b
__device__ float g_hhist[(TT - 1) * BB * HH];   // (d,b,H)
__device__ float g_h[BB * HH];
__device__ float g_c[BB * HH];
__device__ float g_hw4[NKC * BB * HH];          // split-K partials of h @ Wh^T
__device__ float g_g4[NKC * BB * H4];           // split-K partials of gates
__device__ float g_ctx[BB * HH];
__device__ float g_encb[H4];
__device__ float g_decb[H4];
__device__ int   g_sidx[SS * BB];
__device__ int   g_tidx[(TT - 1) * BB];

__device__ __forceinline__ float sigf(float x) { return 1.f / (1.f + expf(-x)); }
__device__ __forceinline__ float tanh_fast(float x) {
    float y; asm("tanh.approx.f32 %0, %1;" : "=f"(y) : "f"(x)); return y;
}

// ---------------- init ----------------------------------------------------------------
__global__ void init_kernel(float* __restrict__ out,
                            const int* __restrict__ src, const int* __restrict__ tgt,
                            const float* __restrict__ ebih, const float* __restrict__ ebhh,
                            const float* __restrict__ dbih, const float* __restrict__ dbhh)
{
    int idx = blockIdx.x * blockDim.x + threadIdx.x;
    if (idx < BB * VTV) {
        int b = idx / VTV, v = idx % VTV;
        out[(size_t)b * TT * VTV + v] = 0.f;
    }
    if (idx < BB * HH) { g_h[idx] = 0.f; g_c[idx] = 0.f; }
    if (idx < SS * BB) { int s = idx >> 5, b = idx & 31; g_sidx[idx] = src[b * SS + s]; }
    if (idx < (TT - 1) * BB) { int d = idx >> 5, b = idx & 31; g_tidx[idx] = tgt[b * TT + d]; }
    if (idx < H4) {
        g_encb[idx] = ebih[idx] + ebhh[idx];
        g_decb[idx] = dbih[idx] + dbhh[idx];
    }
}

// ---------------- big NT GEMM (unchanged from passing R8) -----------------------------
// EPI: 0 = plain store, 1 = +bias[n], 4 = scatter into out[b, d+1, n] with +bias[n]
template<int EPI, bool GATHER>
__global__ void __launch_bounds__(256)
gemm_big(const float* __restrict__ A, int lda,
         const float* __restrict__ Bw, int ldb,
         float* __restrict__ C, int ldc,
         int M, int N, int K,
         const float* __restrict__ bias,
         const int* __restrict__ gidx)
{
    constexpr int BM = 128, BN = 64, BK = 16, TM = 8;
    __shared__ __align__(16) float As[BK][BM + 4];
    __shared__ __align__(16) float Bs[BK][BN + 4];

    const int tid = threadIdx.x;
    const int bm = blockIdx.y * BM;
    const int bn = blockIdx.x * BN;
    const int tx = tid % 16;
    const int ty = tid / 16;

    ull acc[TM][2];
#pragma unroll
    for (int i = 0; i < TM; i++) { acc[i][0] = 0ull; acc[i][1] = 0ull; }

    for (int k0 = 0; k0 < K; k0 += BK) {
        __syncthreads();
#pragma unroll
        for (int it = 0; it < 2; it++) {
            int i = tid + it * 256;
            int r = i / 4, c = (i % 4) * 4;
            int gm = bm + r; if (gm > M - 1) gm = M - 1;
            const float* arow = GATHER ? (A + (size_t)gidx[gm] * lda)
                                       : (A + (size_t)gm * lda);
            float4 v = *reinterpret_cast<const float4*>(arow + k0 + c);
            As[c + 0][r] = v.x; As[c + 1][r] = v.y;
            As[c + 2][r] = v.z; As[c + 3][r] = v.w;
        }
        {
            int r = tid / 4, c = (tid % 4) * 4;
            float4 w = *reinterpret_cast<const float4*>(Bw + (size_t)(bn + r) * ldb + k0 + c);
            Bs[c + 0][r] = w.x; Bs[c + 1][r] = w.y;
            Bs[c + 2][r] = w.z; Bs[c + 3][r] = w.w;
        }
        __syncthreads();
#pragma unroll
        for (int kk = 0; kk < BK; kk++) {
            ull b0 = *reinterpret_cast<const ull*>(&Bs[kk][tx * 4]);
            ull b1 = *reinterpret_cast<const ull*>(&Bs[kk][tx * 4 + 2]);
#pragma unroll
            for (int i = 0; i < TM; i++) {
                float a = As[kk][ty * TM + i];
                ull a2;
                asm("mov.b64 %0, {%1, %1};" : "=l"(a2) : "f"(a));
                asm("fma.rn.f32x2 %0, %1, %2, %0;" : "+l"(acc[i][0]) : "l"(a2), "l"(b0));
                asm("fma.rn.f32x2 %0, %1, %2, %0;" : "+l"(acc[i][1]) : "l"(a2), "l"(b1));
            }
        }
    }

#pragma unroll
    for (int i = 0; i < TM; i++) {
        int gm = bm + ty * TM + i;
        if (gm >= M) continue;
#pragma unroll
        for (int j = 0; j < 2; j++) {
            float2 v = *reinterpret_cast<float2*>(&acc[i][j]);
            int gn = bn + tx * 4 + 2 * j;
            if (EPI == 0) {
                C[(size_t)gm * ldc + gn]     = v.x;
                C[(size_t)gm * ldc + gn + 1] = v.y;
            } else if (EPI == 1) {
                C[(size_t)gm * ldc + gn]     = v.x + bias[gn];
                C[(size_t)gm * ldc + gn + 1] = v.y + bias[gn + 1];
            } else {
                int b = gm & 31, d = gm >> 5;
                size_t o = ((size_t)b * TT + d + 1) * VTV + gn;
                C[o]     = v.x + bias[gn];
                C[o + 1] = v.y + bias[gn + 1];
            }
        }
    }
}

// ---------------- split-K recurrent GEMM: partial[kc][b][n] = sum_{k in chunk} --------
// blockIdx.x = n-tile (32 cols), blockIdx.y = k-chunk. DUAL adds a second (A1,B1) pass.
template<bool DUAL>
__global__ void __launch_bounds__(256)
rec_gemm(const float* __restrict__ A0, const float* __restrict__ B0, int ldb0,
         const float* __restrict__ A1, const float* __restrict__ B1, int ldb1,
         float* __restrict__ Cp, int N, int K)
{
    constexpr int BK = 32;
    const int KC = K / NKC;
    __shared__ __align__(16) float As[BK][36];
    __shared__ __align__(16) float Bs[BK][36];

    const int tid = threadIdx.x;
    const int bn = blockIdx.x * 32;
    const int kc = blockIdx.y;
    const int tx = tid % 16;   // cols: tx*2
    const int ty = tid / 16;   // rows: ty*2

    ull acc[2]; acc[0] = 0ull; acc[1] = 0ull;

    const int npass = DUAL ? 2 : 1;
    for (int p = 0; p < npass; p++) {
        const float* A  = p ? A1 : A0;
        const float* Bw = p ? B1 : B0;
        const int ldb   = p ? ldb1 : ldb0;
        for (int k0 = kc * KC; k0 < (kc + 1) * KC; k0 += BK) {
            __syncthreads();
            {
                int r = tid / 8, c = (tid % 8) * 4;   // 32 rows x 32 k
                float4 v = *reinterpret_cast<const float4*>(A + (size_t)r * K + k0 + c);
                As[c + 0][r] = v.x; As[c + 1][r] = v.y;
                As[c + 2][r] = v.z; As[c + 3][r] = v.w;
                float4 w = *reinterpret_cast<const float4*>(Bw + (size_t)(bn + r) * ldb + k0 + c);
                Bs[c + 0][r] = w.x; Bs[c + 1][r] = w.y;
                Bs[c + 2][r] = w.z; Bs[c + 3][r] = w.w;
            }
            __syncthreads();
#pragma unroll
            for (int kk = 0; kk < BK; kk++) {
                ull b = *reinterpret_cast<const ull*>(&Bs[kk][tx * 2]);
                float a0 = As[kk][ty * 2], a1 = As[kk][ty * 2 + 1];
                ull a2;
                asm("mov.b64 %0, {%1, %1};" : "=l"(a2) : "f"(a0));
                asm("fma.rn.f32x2 %0, %1, %2, %0;" : "+l"(acc[0]) : "l"(a2), "l"(b));
                asm("mov.b64 %0, {%1, %1};" : "=l"(a2) : "f"(a1));
                asm("fma.rn.f32x2 %0, %1, %2, %0;" : "+l"(acc[1]) : "l"(a2), "l"(b));
            }
        }
    }

#pragma unroll
    for (int i = 0; i < 2; i++) {
        int gm = ty * 2 + i;            // batch row
        int gn = bn + tx * 2;
        *reinterpret_cast<float2*>(&Cp[((size_t)kc * BB + gm) * N + gn]) =
            *reinterpret_cast<float2*>(&acc[i]);
    }
}

// ---------------- attention: sum hW partials + tanh scores + softmax + context --------
__global__ void __launch_bounds__(256) attn_kernel(const float* __restrict__ vW)
{
    __shared__ __align__(16) float shW[HH];
    __shared__ __align__(16) float sv[HH];
    __shared__ float sc[SS];
    const int b = blockIdx.x;
    const int tid = threadIdx.x;
    const int lane = tid & 31, warp = tid >> 5;

    for (int j = tid; j < HH; j += 256) {
        float v = 0.f;
#pragma unroll
        for (int kc = 0; kc < NKC; kc++) v += g_hw4[((size_t)kc * BB + b) * HH + j];
        shW[j] = v;
        sv[j] = vW[j];
    }
    __syncthreads();

    for (int s = warp; s < SS; s += 8) {
        const float* ep = g_enc_pre + ((size_t)b * SS + s) * HH;
        float acc = 0.f;
#pragma unroll
        for (int t = 0; t < 8; t++) {
            int j = lane * 4 + t * 128;
            float4 e = *reinterpret_cast<const float4*>(ep + j);
            float4 w = *reinterpret_cast<const float4*>(&shW[j]);
            float4 v = *reinterpret_cast<const float4*>(&sv[j]);
            acc += v.x * tanh_fast(w.x + e.x) + v.y * tanh_fast(w.y + e.y)
                 + v.z * tanh_fast(w.z + e.z) + v.w * tanh_fast(w.w + e.w);
        }
#pragma unroll
        for (int o = 16; o; o >>= 1) acc += __shfl_xor_sync(0xffffffffu, acc, o);
        if (lane == 0) sc[s] = acc;
    }
    __syncthreads();

    if (warp == 0) {                    // parallel softmax over 64 scores
        float v0 = sc[lane], v1 = sc[lane + 32];
        float m = fmaxf(v0, v1);
#pragma unroll
        for (int o = 16; o; o >>= 1) m = fmaxf(m, __shfl_xor_sync(0xffffffffu, m, o));
        float e0 = expf(v0 - m), e1 = expf(v1 - m);
        float su = e0 + e1;
#pragma unroll
        for (int o = 16; o; o >>= 1) su += __shfl_xor_sync(0xffffffffu, su, o);
        float inv = 1.f / su;
        sc[lane] = e0 * inv; sc[lane + 32] = e1 * inv;
    }
    __syncthreads();

    {                                    // context: thread owns 4 consecutive j
        int j0 = tid * 4;
        float4 acc = make_float4(0.f, 0.f, 0.f, 0.f);
        const float* eo = g_enc_out + (size_t)b * SS * HH + j0;
#pragma unroll 8
        for (int s = 0; s < SS; s++) {
            float4 v = *reinterpret_cast<const float4*>(eo + (size_t)s * HH);
            float a = sc[s];
            acc.x += a * v.x; acc.y += a * v.y; acc.z += a * v.z; acc.w += a * v.w;
        }
        *reinterpret_cast<float4*>(&g_ctx[b * HH + j0]) = acc;
    }
}

// ---------------- LSTM: sum 4 gate partials + bias + xg, cell update -------------------
__global__ void __launch_bounds__(256)
lstm4_kernel(const float* __restrict__ xg, const float* __restrict__ bias,
             float* __restrict__ hdst, int bstride)
{
    int idx = blockIdx.x * blockDim.x + threadIdx.x;
    if (idx >= BB * HH) return;
    int b = idx >> 10, j = idx & (HH - 1);
    float gate[4];
#pragma unroll
    for (int g = 0; g < 4; g++) {
        int r = g * HH + j;
        float v = bias[r] + xg[(size_t)b * H4 + r];
#pragma unroll
        for (int kc = 0; kc < NKC; kc++) v += g_g4[((size_t)kc * BB + b) * H4 + r];
        gate[g] = v;
    }
    float c  = g_c[idx];
    float cn = sigf(gate[1]) * c + sigf(gate[0]) * tanhf(gate[2]);
    float hn = sigf(gate[3]) * tanhf(cn);
    g_c[idx] = cn;
    g_h[idx] = hn;
    hdst[(size_t)b * bstride + j] = hn;
}

// ------------------------------------- launch -----------------------------------------
extern "C" void kernel_launch(void* const* d_in, const int* in_sizes, int n_in,
                              void* d_out, int out_size)
{
    const int*   src     = (const int*)d_in[0];
    const int*   tgt     = (const int*)d_in[1];
    const float* enc_emb = (const float*)d_in[2];
    const float* enc_Wih = (const float*)d_in[3];
    const float* enc_Whh = (const float*)d_in[4];
    const float* enc_bih = (const float*)d_in[5];
    const float* enc_bhh = (const float*)d_in[6];
    const float* dec_emb = (const float*)d_in[7];
    const float* attn_W  = (const float*)d_in[8];
    const float* attn_b  = (const float*)d_in[9];
    const float* v_W     = (const float*)d_in[10];
    const float* dec_Wih = (const float*)d_in[11];
    const float* dec_Whh = (const float*)d_in[12];
    const float* dec_bih = (const float*)d_in[13];
    const float* dec_bhh = (const float*)d_in[14];
    const float* fc_W    = (const float*)d_in[15];
    const float* fc_b    = (const float*)d_in[16];
    float* out = (float*)d_out;

    void *pxg, *pdxg, *peo, *pep, *phh, *ph, *pctx, *pg4, *phw4, *peb, *pdb, *psi, *pti;
    cudaGetSymbolAddress(&pxg,  g_enc_xg);
    cudaGetSymbolAddress(&pdxg, g_dxg);
    cudaGetSymbolAddress(&peo,  g_enc_out);
    cudaGetSymbolAddress(&pep,  g_enc_pre);
    cudaGetSymbolAddress(&phh,  g_hhist);
    cudaGetSymbolAddress(&ph,   g_h);
    cudaGetSymbolAddress(&pctx, g_ctx);
    cudaGetSymbolAddress(&pg4,  g_g4);
    cudaGetSymbolAddress(&phw4, g_hw4);
    cudaGetSymbolAddress(&peb,  g_encb);
    cudaGetSymbolAddress(&pdb,  g_decb);
    cudaGetSymbolAddress(&psi,  g_sidx);
    cudaGetSymbolAddress(&pti,  g_tidx);

    float* f_xg  = (float*)pxg;   float* f_dxg = (float*)pdxg;
    float* f_eo  = (float*)peo;   float* f_ep  = (float*)pep;
    float* f_hh  = (float*)phh;   float* f_h   = (float*)ph;
    float* f_ctx = (float*)pctx;  float* f_g4  = (float*)pg4;
    float* f_hw4 = (float*)phw4;  float* f_eb  = (float*)peb;
    float* f_db  = (float*)pdb;
    int*   i_si  = (int*)psi;     int*   i_ti  = (int*)pti;

    // 1. init
    init_kernel<<<(BB * VTV + 255) / 256, 256>>>(out, src, tgt,
                                                 enc_bih, enc_bhh, dec_bih, dec_bhh);

    // 2. encoder input gates: enc_emb[src] @ enc_Wih^T
    {
        dim3 grid(H4 / 64, (SS * BB + 127) / 128);
        gemm_big<0, true><<<grid, 256>>>(enc_emb, EE, enc_Wih, EE,
                                         f_xg, H4, SS * BB, H4, EE, nullptr, i_si);
    }
    // 3. decoder embedding gates: dec_emb[tgt] @ dec_Wih[:, :E]^T
    {
        dim3 grid(H4 / 64, ((TT - 1) * BB + 127) / 128);
        gemm_big<0, true><<<grid, 256>>>(dec_emb, EE, dec_Wih, EE + HH,
                                         f_dxg, H4, (TT - 1) * BB, H4, EE, nullptr, i_ti);
    }

    // 4. encoder recurrence (split-K GEMM + fused-reduce LSTM)
    for (int s = 0; s < SS; s++) {
        rec_gemm<false><<<dim3(H4 / 32, NKC), 256>>>(f_h, enc_Whh, HH,
                                                     nullptr, nullptr, 0,
                                                     f_g4, H4, HH);
        lstm4_kernel<<<BB * HH / 256, 256>>>(f_xg + (size_t)s * BB * H4, f_eb,
                                             f_eo + (size_t)s * HH, SS * HH);
    }

    // 5. enc_pre = enc_out @ We^T + attn_b
    {
        dim3 grid(HH / 64, (BB * SS + 127) / 128);
        gemm_big<1, false><<<grid, 256>>>(f_eo, HH, attn_W + HH, 2 * HH,
                                          f_ep, HH, BB * SS, HH, HH, attn_b, nullptr);
    }

    // 6. decoder recurrence
    for (int d = 0; d < TT - 1; d++) {
        rec_gemm<false><<<dim3(HH / 32, NKC), 256>>>(f_h, attn_W, 2 * HH,
                                                     nullptr, nullptr, 0,
                                                     f_hw4, HH, HH);
        attn_kernel<<<BB, 256>>>(v_W);
        rec_gemm<true><<<dim3(H4 / 32, NKC), 256>>>(f_ctx, dec_Wih + EE, EE + HH,
                                                    f_h, dec_Whh, HH,
                                                    f_g4, H4, HH);
        lstm4_kernel<<<BB * HH / 256, 256>>>(f_dxg + (size_t)d * BB * H4, f_db,
                                             f_hh + (size_t)d * BB * HH, HH);
    }

    // 7. fc logits: out[b, d+1, :] = h_hist @ fc_W^T + fc_b
    {
        dim3 grid(VTV / 64, ((TT - 1) * BB + 127) / 128);
        gemm_big<4, false><<<grid, 256>>>(f_hh, HH, fc_W, HH,
                                          out, VTV, (TT - 1) * BB, VTV, HH, fc_b, nullptr);
    }
}

// round 14
// speedup vs baseline: 1.3975x; 1.1206x over previous
#include <cuda_runtime.h>
#include <math.h>

#define BB 32
#define SS 64
#define TT 64
#define EE 512
#define HH 1024
#define H4 4096
#define VTV 32000
#define NKC 8            // split-K chunks for recurrent GEMMs

typedef unsigned long long ull;

// ---------------- scratch ----------------
__device__ float g_enc_xg[SS * BB * H4];
__device__ float g_dxg[(TT - 1) * BB * H4];
__device__ float g_enc_out[BB * SS * HH];
__device__ float g_enc_pre[BB * SS * HH];
__device__ float g_hhist[(TT - 1) * BB * HH];
__device__ float g_h[BB * HH];
__device__ float g_c[BB * HH];
__device__ float g_hw4[NKC * BB * HH];
__device__ float g_g4[NKC * BB * H4];
__device__ float g_ctx[BB * HH];
__device__ float g_encb[H4];
__device__ float g_decb[H4];
__device__ int   g_sidx[SS * BB];
__device__ int   g_tidx[(TT - 1) * BB];

__device__ __forceinline__ float sigf(float x) { return 1.f / (1.f + expf(-x)); }
__device__ __forceinline__ float tanh_fast(float x) {
    float y; asm("tanh.approx.f32 %0, %1;" : "=f"(y) : "f"(x)); return y;
}
__device__ __forceinline__ void fma2(ull& acc, ull a, ull b) {
    asm("fma.rn.f32x2 %0, %1, %2, %0;" : "+l"(acc) : "l"(a), "l"(b));
}
__device__ __forceinline__ float lohi(ull a) {
    float2 v = *reinterpret_cast<float2*>(&a); return v.x + v.y;
}

// ---------------- init ----------------
__global__ void init_kernel(float* __restrict__ out,
                            const int* __restrict__ src, const int* __restrict__ tgt,
                            const float* __restrict__ ebih, const float* __restrict__ ebhh,
                            const float* __restrict__ dbih, const float* __restrict__ dbhh)
{
    int idx = blockIdx.x * blockDim.x + threadIdx.x;
    if (idx < BB * VTV) {
        int b = idx / VTV, v = idx % VTV;
        out[(size_t)b * TT * VTV + v] = 0.f;
    }
    if (idx < BB * HH) { g_h[idx] = 0.f; g_c[idx] = 0.f; }
    if (idx < SS * BB) { int s = idx >> 5, b = idx & 31; g_sidx[idx] = src[b * SS + s]; }
    if (idx < (TT - 1) * BB) { int d = idx >> 5, b = idx & 31; g_tidx[idx] = tgt[b * TT + d]; }
    if (idx < H4) {
        g_encb[idx] = ebih[idx] + ebhh[idx];
        g_decb[idx] = dbih[idx] + dbhh[idx];
    }
}

// ---------------- big NT GEMM: k-pair f32x2, reg double-buffered ----------------
// EPI: 0 plain, 1 +bias[n], 4 scatter out[b,d+1,n] (+bias)
template<int EPI, bool GATHER>
__global__ void __launch_bounds__(256, 2)
gemm_big(const float* __restrict__ A, int lda,
         const float* __restrict__ Bw, int ldb,
         float* __restrict__ C, int ldc,
         int M, int N, int K,
         const float* __restrict__ bias,
         const int* __restrict__ gidx)
{
    constexpr int BM = 128, BN = 64, BK = 32, LDT = BK + 2;
    __shared__ __align__(16) float As[BM * LDT];
    __shared__ __align__(16) float Bs[BN * LDT];

    const int tid = threadIdx.x;
    const int bm = blockIdx.y * BM;
    const int bn = blockIdx.x * BN;
    const int tx = tid & 15;   // owns cols bn + tx + 16j, j<4
    const int ty = tid >> 4;   // owns rows bm + ty + 16i, i<8
    const int lr = tid >> 3, lc = (tid & 7) * 4;   // load coords

    ull acc[8][4];
#pragma unroll
    for (int i = 0; i < 8; i++)
#pragma unroll
        for (int j = 0; j < 4; j++) acc[i][j] = 0ull;

    float4 pa[4], pb[2];
    const int KT = K / BK;

#define LOAD_TILE(k0)                                                           \
    {                                                                           \
        _Pragma("unroll")                                                       \
        for (int it = 0; it < 4; it++) {                                        \
            int r = lr + it * 32;                                               \
            int gm = bm + r; if (gm > M - 1) gm = M - 1;                        \
            const float* ar = GATHER ? (A + (size_t)gidx[gm] * lda)             \
                                     : (A + (size_t)gm * lda);                  \
            pa[it] = *reinterpret_cast<const float4*>(ar + (k0) + lc);          \
        }                                                                       \
        _Pragma("unroll")                                                       \
        for (int it = 0; it < 2; it++) {                                        \
            int r = lr + it * 32;                                               \
            pb[it] = *reinterpret_cast<const float4*>(Bw + (size_t)(bn + r) * ldb + (k0) + lc); \
        }                                                                       \
    }

    LOAD_TILE(0)
    for (int kt = 0; kt < KT; kt++) {
        __syncthreads();
#pragma unroll
        for (int it = 0; it < 4; it++) {
            int r = lr + it * 32;
            *reinterpret_cast<float2*>(&As[r * LDT + lc])     = make_float2(pa[it].x, pa[it].y);
            *reinterpret_cast<float2*>(&As[r * LDT + lc + 2]) = make_float2(pa[it].z, pa[it].w);
        }
#pragma unroll
        for (int it = 0; it < 2; it++) {
            int r = lr + it * 32;
            *reinterpret_cast<float2*>(&Bs[r * LDT + lc])     = make_float2(pb[it].x, pb[it].y);
            *reinterpret_cast<float2*>(&Bs[r * LDT + lc + 2]) = make_float2(pb[it].z, pb[it].w);
        }
        __syncthreads();
        if (kt + 1 < KT) LOAD_TILE((kt + 1) * BK)
#pragma unroll
        for (int kk = 0; kk < BK / 2; kk++) {
            ull av[8], bv[4];
#pragma unroll
            for (int i = 0; i < 8; i++)
                av[i] = *reinterpret_cast<const ull*>(&As[(ty + 16 * i) * LDT + 2 * kk]);
#pragma unroll
            for (int j = 0; j < 4; j++)
                bv[j] = *reinterpret_cast<const ull*>(&Bs[(tx + 16 * j) * LDT + 2 * kk]);
#pragma unroll
            for (int i = 0; i < 8; i++)
#pragma unroll
                for (int j = 0; j < 4; j++) fma2(acc[i][j], av[i], bv[j]);
        }
    }
#undef LOAD_TILE

#pragma unroll
    for (int i = 0; i < 8; i++) {
        int gm = bm + ty + 16 * i;
        if (gm >= M) continue;
#pragma unroll
        for (int j = 0; j < 4; j++) {
            float v = lohi(acc[i][j]);
            int gn = bn + tx + 16 * j;
            if (EPI == 0) {
                C[(size_t)gm * ldc + gn] = v;
            } else if (EPI == 1) {
                C[(size_t)gm * ldc + gn] = v + bias[gn];
            } else {
                int b = gm & 31, d = gm >> 5;
                C[((size_t)b * TT + d + 1) * VTV + gn] = v + bias[gn];
            }
        }
    }
}

// ---------------- split-K recurrent GEMM: k-pair f32x2, reg double-buffered ----------
// partial[kc][b][n]; blockIdx.x = n-tile(32), blockIdx.y = k-chunk. DUAL adds 2nd pass.
template<bool DUAL>
__global__ void __launch_bounds__(256)
rec_gemm(const float* __restrict__ A0, const float* __restrict__ B0, int ldb0,
         const float* __restrict__ A1, const float* __restrict__ B1, int ldb1,
         float* __restrict__ Cp, int N, int K)
{
    constexpr int BK = 32, LDT = BK + 2;
    __shared__ __align__(16) float As[BB * LDT];
    __shared__ __align__(16) float Bs[BB * LDT];

    const int tid = threadIdx.x;
    const int bn = blockIdx.x * 32;
    const int kc = blockIdx.y;
    const int tx = tid & 15;   // cols bn + tx + 16j
    const int ty = tid >> 4;   // rows ty + 16i (batch)
    const int lr = tid >> 3, lc = (tid & 7) * 4;
    const int KC = K / NKC;

    ull acc[2][2];
    acc[0][0] = acc[0][1] = acc[1][0] = acc[1][1] = 0ull;

    const int npass = DUAL ? 2 : 1;
    for (int p = 0; p < npass; p++) {
        const float* A  = p ? A1 : A0;
        const float* Bw = p ? B1 : B0;
        const int ldb   = p ? ldb1 : ldb0;
        const int kbeg  = kc * KC;
        const int KT    = KC / BK;

        float4 pa, pb;
        pa = *reinterpret_cast<const float4*>(A + (size_t)lr * K + kbeg + lc);
        pb = *reinterpret_cast<const float4*>(Bw + (size_t)(bn + lr) * ldb + kbeg + lc);

        for (int kt = 0; kt < KT; kt++) {
            __syncthreads();
            *reinterpret_cast<float2*>(&As[lr * LDT + lc])     = make_float2(pa.x, pa.y);
            *reinterpret_cast<float2*>(&As[lr * LDT + lc + 2]) = make_float2(pa.z, pa.w);
            *reinterpret_cast<float2*>(&Bs[lr * LDT + lc])     = make_float2(pb.x, pb.y);
            *reinterpret_cast<float2*>(&Bs[lr * LDT + lc + 2]) = make_float2(pb.z, pb.w);
            __syncthreads();
            if (kt + 1 < KT) {
                int k0 = kbeg + (kt + 1) * BK;
                pa = *reinterpret_cast<const float4*>(A + (size_t)lr * K + k0 + lc);
                pb = *reinterpret_cast<const float4*>(Bw + (size_t)(bn + lr) * ldb + k0 + lc);
            }
#pragma unroll
            for (int kk = 0; kk < BK / 2; kk++) {
                ull av0 = *reinterpret_cast<const ull*>(&As[ty * LDT + 2 * kk]);
                ull av1 = *reinterpret_cast<const ull*>(&As[(ty + 16) * LDT + 2 * kk]);
                ull bv0 = *reinterpret_cast<const ull*>(&Bs[tx * LDT + 2 * kk]);
                ull bv1 = *reinterpret_cast<const ull*>(&Bs[(tx + 16) * LDT + 2 * kk]);
                fma2(acc[0][0], av0, bv0); fma2(acc[0][1], av0, bv1);
                fma2(acc[1][0], av1, bv0); fma2(acc[1][1], av1, bv1);
            }
        }
    }

#pragma unroll
    for (int i = 0; i < 2; i++)
#pragma unroll
        for (int j = 0; j < 2; j++) {
            int gm = ty + 16 * i;
            int gn = bn + tx + 16 * j;
            Cp[((size_t)kc * BB + gm) * N + gn] = lohi(acc[i][j]);
        }
}

// ---------------- attention ----------------
__global__ void __launch_bounds__(256) attn_kernel(const float* __restrict__ vW)
{
    __shared__ __align__(16) float shW[HH];
    __shared__ __align__(16) float sv[HH];
    __shared__ float sc[SS];
    const int b = blockIdx.x;
    const int tid = threadIdx.x;
    const int lane = tid & 31, warp = tid >> 5;

    for (int j = tid; j < HH; j += 256) {
        float v = 0.f;
#pragma unroll
        for (int kc = 0; kc < NKC; kc++) v += g_hw4[((size_t)kc * BB + b) * HH + j];
        shW[j] = v;
        sv[j] = vW[j];
    }
    __syncthreads();

    for (int s = warp; s < SS; s += 8) {
        const float* ep = g_enc_pre + ((size_t)b * SS + s) * HH;
        float acc = 0.f;
#pragma unroll
        for (int t = 0; t < 8; t++) {
            int j = lane * 4 + t * 128;
            float4 e = *reinterpret_cast<const float4*>(ep + j);
            float4 w = *reinterpret_cast<const float4*>(&shW[j]);
            float4 v = *reinterpret_cast<const float4*>(&sv[j]);
            acc += v.x * tanh_fast(w.x + e.x) + v.y * tanh_fast(w.y + e.y)
                 + v.z * tanh_fast(w.z + e.z) + v.w * tanh_fast(w.w + e.w);
        }
#pragma unroll
        for (int o = 16; o; o >>= 1) acc += __shfl_xor_sync(0xffffffffu, acc, o);
        if (lane == 0) sc[s] = acc;
    }
    __syncthreads();

    if (warp == 0) {
        float v0 = sc[lane], v1 = sc[lane + 32];
        float m = fmaxf(v0, v1);
#pragma unroll
        for (int o = 16; o; o >>= 1) m = fmaxf(m, __shfl_xor_sync(0xffffffffu, m, o));
        float e0 = expf(v0 - m), e1 = expf(v1 - m);
        float su = e0 + e1;
#pragma unroll
        for (int o = 16; o; o >>= 1) su += __shfl_xor_sync(0xffffffffu, su, o);
        float inv = 1.f / su;
        sc[lane] = e0 * inv; sc[lane + 32] = e1 * inv;
    }
    __syncthreads();

    {
        int j0 = tid * 4;
        float4 acc = make_float4(0.f, 0.f, 0.f, 0.f);
        const float* eo = g_enc_out + (size_t)b * SS * HH + j0;
#pragma unroll 8
        for (int s = 0; s < SS; s++) {
            float4 v = *reinterpret_cast<const float4*>(eo + (size_t)s * HH);
            float a = sc[s];
            acc.x += a * v.x; acc.y += a * v.y; acc.z += a * v.z; acc.w += a * v.w;
        }
        *reinterpret_cast<float4*>(&g_ctx[b * HH + j0]) = acc;
    }
}

// ---------------- LSTM: sum NKC gate partials + bias + xg, cell update ----------------
__global__ void __launch_bounds__(256)
lstm4_kernel(const float* __restrict__ xg, const float* __restrict__ bias,
             float* __restrict__ hdst, int bstride)
{
    int idx = blockIdx.x * blockDim.x + threadIdx.x;
    if (idx >= BB * HH) return;
    int b = idx >> 10, j = idx & (HH - 1);
    float gate[4];
#pragma unroll
    for (int g = 0; g < 4; g++) {
        int r = g * HH + j;
        float v = bias[r] + xg[(size_t)b * H4 + r];
#pragma unroll
        for (int kc = 0; kc < NKC; kc++) v += g_g4[((size_t)kc * BB + b) * H4 + r];
        gate[g] = v;
    }
    float c  = g_c[idx];
    float cn = sigf(gate[1]) * c + sigf(gate[0]) * tanhf(gate[2]);
    float hn = sigf(gate[3]) * tanhf(cn);
    g_c[idx] = cn;
    g_h[idx] = hn;
    hdst[(size_t)b * bstride + j] = hn;
}

// ------------------------------------- launch -----------------------------------------
extern "C" void kernel_launch(void* const* d_in, const int* in_sizes, int n_in,
                              void* d_out, int out_size)
{
    const int*   src     = (const int*)d_in[0];
    const int*   tgt     = (const int*)d_in[1];
    const float* enc_emb = (const float*)d_in[2];
    const float* enc_Wih = (const float*)d_in[3];
    const float* enc_Whh = (const float*)d_in[4];
    const float* enc_bih = (const float*)d_in[5];
    const float* enc_bhh = (const float*)d_in[6];
    const float* dec_emb = (const float*)d_in[7];
    const float* attn_W  = (const float*)d_in[8];
    const float* attn_b  = (const float*)d_in[9];
    const float* v_W     = (const float*)d_in[10];
    const float* dec_Wih = (const float*)d_in[11];
    const float* dec_Whh = (const float*)d_in[12];
    const float* dec_bih = (const float*)d_in[13];
    const float* dec_bhh = (const float*)d_in[14];
    const float* fc_W    = (const float*)d_in[15];
    const float* fc_b    = (const float*)d_in[16];
    float* out = (float*)d_out;

    void *pxg, *pdxg, *peo, *pep, *phh, *ph, *pctx, *pg4, *phw4, *peb, *pdb, *psi, *pti;
    cudaGetSymbolAddress(&pxg,  g_enc_xg);
    cudaGetSymbolAddress(&pdxg, g_dxg);
    cudaGetSymbolAddress(&peo,  g_enc_out);
    cudaGetSymbolAddress(&pep,  g_enc_pre);
    cudaGetSymbolAddress(&phh,  g_hhist);
    cudaGetSymbolAddress(&ph,   g_h);
    cudaGetSymbolAddress(&pctx, g_ctx);
    cudaGetSymbolAddress(&pg4,  g_g4);
    cudaGetSymbolAddress(&phw4, g_hw4);
    cudaGetSymbolAddress(&peb,  g_encb);
    cudaGetSymbolAddress(&pdb,  g_decb);
    cudaGetSymbolAddress(&psi,  g_sidx);
    cudaGetSymbolAddress(&pti,  g_tidx);

    float* f_xg  = (float*)pxg;   float* f_dxg = (float*)pdxg;
    float* f_eo  = (float*)peo;   float* f_ep  = (float*)pep;
    float* f_hh  = (float*)phh;   float* f_h   = (float*)ph;
    float* f_ctx = (float*)pctx;  float* f_g4  = (float*)pg4;
    float* f_hw4 = (float*)phw4;  float* f_eb  = (float*)peb;
    float* f_db  = (float*)pdb;
    int*   i_si  = (int*)psi;     int*   i_ti  = (int*)pti;

    // 1. init
    init_kernel<<<(BB * VTV + 255) / 256, 256>>>(out, src, tgt,
                                                 enc_bih, enc_bhh, dec_bih, dec_bhh);

    // 2. encoder input gates: enc_emb[src] @ enc_Wih^T
    {
        dim3 grid(H4 / 64, (SS * BB + 127) / 128);
        gemm_big<0, true><<<grid, 256>>>(enc_emb, EE, enc_Wih, EE,
                                         f_xg, H4, SS * BB, H4, EE, nullptr, i_si);
    }
    // 3. decoder embedding gates: dec_emb[tgt] @ dec_Wih[:, :E]^T
    {
        dim3 grid(H4 / 64, ((TT - 1) * BB + 127) / 128);
        gemm_big<0, true><<<grid, 256>>>(dec_emb, EE, dec_Wih, EE + HH,
                                         f_dxg, H4, (TT - 1) * BB, H4, EE, nullptr, i_ti);
    }

    // 4. encoder recurrence
    for (int s = 0; s < SS; s++) {
        rec_gemm<false><<<dim3(H4 / 32, NKC), 256>>>(f_h, enc_Whh, HH,
                                                     nullptr, nullptr, 0,
                                                     f_g4, H4, HH);
        lstm4_kernel<<<BB * HH / 256, 256>>>(f_xg + (size_t)s * BB * H4, f_eb,
                                             f_eo + (size_t)s * HH, SS * HH);
    }

    // 5. enc_pre = enc_out @ We^T + attn_b
    {
        dim3 grid(HH / 64, (BB * SS + 127) / 128);
        gemm_big<1, false><<<grid, 256>>>(f_eo, HH, attn_W + HH, 2 * HH,
                                          f_ep, HH, BB * SS, HH, HH, attn_b, nullptr);
    }

    // 6. decoder recurrence
    for (int d = 0; d < TT - 1; d++) {
        rec_gemm<false><<<dim3(HH / 32, NKC), 256>>>(f_h, attn_W, 2 * HH,
                                                     nullptr, nullptr, 0,
                                                     f_hw4, HH, HH);
        attn_kernel<<<BB, 256>>>(v_W);
        rec_gemm<true><<<dim3(H4 / 32, NKC), 256>>>(f_ctx, dec_Wih + EE, EE + HH,
                                                    f_h, dec_Whh, HH,
                                                    f_g4, H4, HH);
        lstm4_kernel<<<BB * HH / 256, 256>>>(f_dxg + (size_t)d * BB * H4, f_db,
                                             f_hh + (size_t)d * BB * HH, HH);
    }

    // 7. fc logits: out[b, d+1, :] = h_hist @ fc_W^T + fc_b
    {
        dim3 grid(VTV / 64, ((TT - 1) * BB + 127) / 128);
        gemm_big<4, false><<<grid, 256>>>(f_hh, HH, fc_W, HH,
                                          out, VTV, (TT - 1) * BB, VTV, HH, fc_b, nullptr);
    }
}